// round 15
// baseline (speedup 1.0000x reference)
#include <cuda_runtime.h>
#include <math.h>

#define IN_F   1024
#define OUT_F  512
#define BATCH  256
#define TLO    0.04f
#define THI    0.96f

// no_edge bit matrix, o-major: g_bits[o*32 + iw], bit = i&31. 64 KB.
__device__ unsigned g_bits[OUT_F * 32];

// ---------------------------------------------------------------------------
// no_edge = argmax(etc + gumbel(u)) == 1, i.e. (etc1+g1) > (etc0+g0) strictly
// (argmax tie -> index 0). g(u) = -log(-log(u+eps)+eps) is strictly
// increasing, so for etc0==etc1 this is exactly u1>u0; full gumbel math as
// the general fallback.
// ---------------------------------------------------------------------------
__device__ __forceinline__ bool no_edge_of(float e0, float e1, float u0, float u1) {
    if (e0 == e1) return u1 > u0;
    const float eps = 1e-10f;
    float g0 = -logf(-logf(u0 + eps) + eps);
    float g1 = -logf(-logf(u1 + eps) + eps);
    return (e1 + g1) > (e0 + g0);
}

// ---------------------------------------------------------------------------
// Mask build. Block = 32(o) x 64(i) tile; 8 upfront LDG.128 per thread
// (MLP 8) — identical loads/compute to the proven R13 kernel; only the final
// ballot maps lanes over i (non-transposed store: one word per (o, iw)).
// ---------------------------------------------------------------------------
__global__ __launch_bounds__(256)
void fused_mask_kernel(const float* __restrict__ etc, const float* __restrict__ un) {
    __shared__ unsigned bits[64][33];   // [i_local][o_local], padded

    const int t    = threadIdx.x;
    const int lane = t & 31;
    const int w    = t >> 5;
    const int ow   = blockIdx.x & 15;   // o-group (32 outputs)
    const int it   = blockIdx.x >> 4;   // 64-wide i-tile

    const int o_local = t >> 3;
    const int i_local = (t & 7) << 2;
    const size_t gp0 = (size_t)(ow * 32 + o_local) * IN_F + (it * 64 + i_local);
    const size_t f0  = gp0 >> 1;
    const size_t f1  = f0 + 16;

    float4 ea0 = ((const float4*)etc)[f0];
    float4 eb0 = ((const float4*)etc)[f0 + 1];
    float4 ea1 = ((const float4*)etc)[f1];
    float4 eb1 = ((const float4*)etc)[f1 + 1];
    float4 ua0 = ((const float4*)un)[f0];
    float4 ub0 = ((const float4*)un)[f0 + 1];
    float4 ua1 = ((const float4*)un)[f1];
    float4 ub1 = ((const float4*)un)[f1 + 1];

    bits[i_local + 0][o_local]      = no_edge_of(ea0.x, ea0.y, ua0.x, ua0.y) ? 1u : 0u;
    bits[i_local + 1][o_local]      = no_edge_of(ea0.z, ea0.w, ua0.z, ua0.w) ? 1u : 0u;
    bits[i_local + 2][o_local]      = no_edge_of(eb0.x, eb0.y, ub0.x, ub0.y) ? 1u : 0u;
    bits[i_local + 3][o_local]      = no_edge_of(eb0.z, eb0.w, ub0.z, ub0.w) ? 1u : 0u;
    bits[i_local + 32 + 0][o_local] = no_edge_of(ea1.x, ea1.y, ua1.x, ua1.y) ? 1u : 0u;
    bits[i_local + 32 + 1][o_local] = no_edge_of(ea1.z, ea1.w, ua1.z, ua1.w) ? 1u : 0u;
    bits[i_local + 32 + 2][o_local] = no_edge_of(eb1.x, eb1.y, ub1.x, ub1.y) ? 1u : 0u;
    bits[i_local + 32 + 3][o_local] = no_edge_of(eb1.z, eb1.w, ub1.z, ub1.w) ? 1u : 0u;

    __syncthreads();

    // Warp w emits 8 (o_local, iw_local) words; lane = i within the word.
    #pragma unroll
    for (int r = 0; r < 8; r++) {
        const int idx = (w << 3) + r;       // 0..63
        const int ol  = idx >> 1;           // 0..31
        const int iwl = idx & 1;            // 0..1
        unsigned word = __ballot_sync(0xFFFFFFFFu, bits[iwl * 32 + lane][ol] != 0u);
        if (lane == 0) g_bits[(size_t)(ow * 32 + ol) * 32 + (it * 2 + iwl)] = word;
    }
}

// ---------------------------------------------------------------------------
// Select: one block per batch, 512 threads; t<256 -> min output o=2t,
// t>=256 -> max output o=2(t-256)+1.
// Candidate BITMAPS (no atomics/compaction/sort/CAP): ballot i=t and i=t+512
// -> cnd[side][0..31]. Each thread loads its own 128B mask row (8 x uint4,
// MLP 8, L1-resident after first block/SM), walks set bits of cand & ~mask
// (E ~20) with LDS + fmin/fmax = exact extremum over unmasked candidates.
// Deterministic fallback (prob ~8e-10/output): walk ~mask bits over xsh
// (mask already in registers). Clamp to identity offsets (2 / -1) handles
// all-no-edge rows exactly.
// ---------------------------------------------------------------------------
__global__ __launch_bounds__(512)
void select_kernel(const float* __restrict__ x, float* __restrict__ out) {
    __shared__ float    xsh[IN_F];
    __shared__ unsigned cnd[2][32];
    __shared__ float    so_out[OUT_F];

    const int t    = threadIdx.x;
    const int lane = t & 31;
    const int w    = t >> 5;
    const int b    = blockIdx.x;

    // Stage x row (coalesced float2 per thread)
    float2 v2 = ((const float2*)(x + (size_t)b * IN_F))[t];
    ((float2*)xsh)[t] = v2;
    __syncthreads();

    // Candidate bitmaps via ballots: lane l of warp w covers i = w*32+l and
    // i = 512 + w*32+l.
    {
        float a0 = xsh[t];
        float a1 = xsh[t + 512];
        unsigned lo0 = __ballot_sync(0xFFFFFFFFu, a0 < TLO);
        unsigned lo1 = __ballot_sync(0xFFFFFFFFu, a1 < TLO);
        unsigned hi0 = __ballot_sync(0xFFFFFFFFu, a0 > THI);
        unsigned hi1 = __ballot_sync(0xFFFFFFFFu, a1 > THI);
        if (lane == 0) {
            cnd[0][w]      = lo0;
            cnd[0][16 + w] = lo1;
            cnd[1][w]      = hi0;
            cnd[1][16 + w] = hi1;
        }
    }
    __syncthreads();

    const int side = t >> 8;            // 0 = min, 1 = max
    const int tl   = t & 255;
    const int o    = 2 * tl + side;

    // Load this output's full mask row: 32 words = 8 independent uint4 LDGs.
    const uint4* __restrict__ mrow = (const uint4*)(g_bits + (size_t)o * 32);
    uint4 q0 = __ldg(mrow + 0), q1 = __ldg(mrow + 1);
    uint4 q2 = __ldg(mrow + 2), q3 = __ldg(mrow + 3);
    uint4 q4 = __ldg(mrow + 4), q5 = __ldg(mrow + 5);
    uint4 q6 = __ldg(mrow + 6), q7 = __ldg(mrow + 7);
    unsigned m[32] = {
        q0.x, q0.y, q0.z, q0.w,  q1.x, q1.y, q1.z, q1.w,
        q2.x, q2.y, q2.z, q2.w,  q3.x, q3.y, q3.z, q3.w,
        q4.x, q4.y, q4.z, q4.w,  q5.x, q5.y, q5.z, q5.w,
        q6.x, q6.y, q6.z, q6.w,  q7.x, q7.y, q7.z, q7.w };

    const float INF  = __int_as_float(0x7F800000);
    const float NINF = __int_as_float(0xFF800000);
    const float init = side ? NINF : INF;

    float acc = init;
    if (side) {
        #pragma unroll
        for (int iw = 0; iw < 32; iw++) {
            unsigned wv = cnd[1][iw] & ~m[iw];
            while (wv) {
                int bit = __ffs(wv) - 1;  wv &= wv - 1;
                acc = fmaxf(acc, xsh[(iw << 5) + bit]);
            }
        }
    } else {
        #pragma unroll
        for (int iw = 0; iw < 32; iw++) {
            unsigned wv = cnd[0][iw] & ~m[iw];
            while (wv) {
                int bit = __ffs(wv) - 1;  wv &= wv - 1;
                acc = fminf(acc, xsh[(iw << 5) + bit]);
            }
        }
    }

    if (acc == init) {   // no unmasked candidate: full masked scan (regs + LDS)
        if (side) {
            #pragma unroll
            for (int iw = 0; iw < 32; iw++) {
                unsigned wv = ~m[iw];
                while (wv) {
                    int bit = __ffs(wv) - 1;  wv &= wv - 1;
                    acc = fmaxf(acc, xsh[(iw << 5) + bit]);
                }
            }
        } else {
            #pragma unroll
            for (int iw = 0; iw < 32; iw++) {
                unsigned wv = ~m[iw];
                while (wv) {
                    int bit = __ffs(wv) - 1;  wv &= wv - 1;
                    acc = fminf(acc, xsh[(iw << 5) + bit]);
                }
            }
        }
    }

    so_out[o] = side ? fmaxf(acc, -1.0f) : fminf(acc, 2.0f);
    __syncthreads();

    // Coalesced float4 store
    if (t < OUT_F / 4) {
        ((float4*)(out + (size_t)b * OUT_F))[t] = ((const float4*)so_out)[t];
    }
}

extern "C" void kernel_launch(void* const* d_in, const int* in_sizes, int n_in,
                              void* d_out, int out_size) {
    const float* x   = (const float*)d_in[0];  // [256, 1024]
    const float* etc = (const float*)d_in[1];  // [512, 1024, 2]
    const float* un  = (const float*)d_in[2];  // [512, 1024, 2]
    float* out = (float*)d_out;                // [256, 512]

    fused_mask_kernel<<<(OUT_F / 32) * (IN_F / 64), 256>>>(etc, un);  // 256 blocks
    select_kernel<<<BATCH, 512>>>(x, out);                            // 256 blocks
}

// round 16
// speedup vs baseline: 1.3400x; 1.3400x over previous
#include <cuda_runtime.h>
#include <math.h>

#define IN_F   1024
#define OUT_F  512
#define BATCH  256
#define CAP    96
#define TLO    0.04f
#define THI    0.96f

// Transposed no_edge bit matrix: [i][o_word], bit = o&31. 64 KB.
__device__ unsigned g_maskT[IN_F * (OUT_F / 32)];
// Monotonic counters (never reset; graph replays are stream-serialized).
__device__ unsigned g_mask_done;   // +256 per launch (one per mask block)
__device__ unsigned g_sel_ticket;  // +256 per launch (one per select block)

// ---------------------------------------------------------------------------
// no_edge = argmax(etc + gumbel(u)) == 1, i.e. (etc1+g1) > (etc0+g0) strictly
// (argmax tie -> index 0). g(u) = -log(-log(u+eps)+eps) is strictly
// increasing, so for etc0==etc1 this is exactly u1>u0; full gumbel math as
// the general fallback.
// ---------------------------------------------------------------------------
__device__ __forceinline__ bool no_edge_of(float e0, float e1, float u0, float u1) {
    if (e0 == e1) return u1 > u0;
    const float eps = 1e-10f;
    float g0 = -logf(-logf(u0 + eps) + eps);
    float g1 = -logf(-logf(u1 + eps) + eps);
    return (e1 + g1) > (e0 + g0);
}

// ---------------------------------------------------------------------------
// Single fused kernel, 512 blocks x 256 threads, two roles:
//   blocks 0..255  : mask tile build (proven R13 code) + arrival
//   blocks 256..511: select for batch bid-256 — extract + sort FIRST
//                    (overlaps mask build), then low-rate poll (1us backoff,
//                    thread 0 only), then staged scan resolve.
// All 512 blocks co-resident (smem ~26KB -> 8 blocks/SM -> 1184 slots), so
// the wait cannot starve mask blocks: deadlock-free by capacity.
// ---------------------------------------------------------------------------
__global__ __launch_bounds__(256)
void daa_kernel(const float* __restrict__ etc, const float* __restrict__ un,
                const float* __restrict__ x, float* __restrict__ out) {
    __shared__ unsigned bits[64][33];          // mask role
    __shared__ float    cv[2][CAP];            // select role
    __shared__ int      ci[2][CAP];
    __shared__ float    sv[2][CAP];
    __shared__ int      sci[2][CAP];
    __shared__ unsigned cm[2][CAP][16];
    __shared__ float    so_out[OUT_F];
    __shared__ int      n_s[2];
    __shared__ unsigned tgt_s;

    const int t    = threadIdx.x;
    const int lane = t & 31;
    const int w    = t >> 5;

    if (blockIdx.x < 256) {
        // ================= mask tile role (R13 verbatim) =================
        const int bid = blockIdx.x;
        const int ow  = bid & 15;              // o-word index (OUT_F/32)
        const int it  = bid >> 4;              // 64-wide i-tile index

        const int o_local = t >> 3;
        const int i_local = (t & 7) << 2;
        const size_t gp0 = (size_t)(ow * 32 + o_local) * IN_F + (it * 64 + i_local);
        const size_t f0  = gp0 >> 1;
        const size_t f1  = f0 + 16;

        float4 ea0 = ((const float4*)etc)[f0];
        float4 eb0 = ((const float4*)etc)[f0 + 1];
        float4 ea1 = ((const float4*)etc)[f1];
        float4 eb1 = ((const float4*)etc)[f1 + 1];
        float4 ua0 = ((const float4*)un)[f0];
        float4 ub0 = ((const float4*)un)[f0 + 1];
        float4 ua1 = ((const float4*)un)[f1];
        float4 ub1 = ((const float4*)un)[f1 + 1];

        bits[i_local + 0][o_local]      = no_edge_of(ea0.x, ea0.y, ua0.x, ua0.y) ? 1u : 0u;
        bits[i_local + 1][o_local]      = no_edge_of(ea0.z, ea0.w, ua0.z, ua0.w) ? 1u : 0u;
        bits[i_local + 2][o_local]      = no_edge_of(eb0.x, eb0.y, ub0.x, ub0.y) ? 1u : 0u;
        bits[i_local + 3][o_local]      = no_edge_of(eb0.z, eb0.w, ub0.z, ub0.w) ? 1u : 0u;
        bits[i_local + 32 + 0][o_local] = no_edge_of(ea1.x, ea1.y, ua1.x, ua1.y) ? 1u : 0u;
        bits[i_local + 32 + 1][o_local] = no_edge_of(ea1.z, ea1.w, ua1.z, ua1.w) ? 1u : 0u;
        bits[i_local + 32 + 2][o_local] = no_edge_of(eb1.x, eb1.y, ub1.x, ub1.y) ? 1u : 0u;
        bits[i_local + 32 + 3][o_local] = no_edge_of(eb1.z, eb1.w, ub1.z, ub1.w) ? 1u : 0u;

        __syncthreads();

        #pragma unroll
        for (int r = 0; r < 8; r++) {
            const int i = (w << 3) + r;
            unsigned word = __ballot_sync(0xFFFFFFFFu, bits[i][lane] != 0u);
            if (lane == 0) g_maskT[(size_t)(it * 64 + i) * 16 + ow] = word;
        }
        __syncthreads();
        if (t == 0) {
            __threadfence();                       // release maskT stores
            atomicAdd(&g_mask_done, 1u);
        }
    } else {
        // ======================= select role =======================
        const int b = blockIdx.x - 256;
        if (t == 0) {
            // Per-launch epoch: tickets of this launch are [256N, 256N+255].
            unsigned tk = atomicAdd(&g_sel_ticket, 1u);
            tgt_s = (tk / 256u + 1u) * 256u;       // g_mask_done target
            n_s[0] = 0; n_s[1] = 0;
        }
        __syncthreads();

        // ---- extraction (mask-independent; overlaps mask build) ----
        float4 v4 = ((const float4*)(x + (size_t)b * IN_F))[t];
        float vals[4] = {v4.x, v4.y, v4.z, v4.w};
        #pragma unroll
        for (int j = 0; j < 4; j++) {
            float v = vals[j];
            int   i = 4 * t + j;

            unsigned mlo = __ballot_sync(0xFFFFFFFFu, v < TLO);
            if (v < TLO) {
                int rank = __popc(mlo & ((1u << lane) - 1u));
                int base = 0, lead = __ffs(mlo) - 1;
                if (lane == lead) base = atomicAdd(&n_s[0], __popc(mlo));
                base = __shfl_sync(mlo, base, lead);
                int p = base + rank;
                if (p < CAP) { cv[0][p] = v; ci[0][p] = i; }
            }
            unsigned mhi = __ballot_sync(0xFFFFFFFFu, v > THI);
            if (v > THI) {
                int rank = __popc(mhi & ((1u << lane) - 1u));
                int base = 0, lead = __ffs(mhi) - 1;
                if (lane == lead) base = atomicAdd(&n_s[1], __popc(mhi));
                base = __shfl_sync(mhi, base, lead);
                int p = base + rank;
                if (p < CAP) { cv[1][p] = v; ci[1][p] = i; }
            }
        }
        __syncthreads();

        const int n0 = min(n_s[0], CAP);
        const int n1 = min(n_s[1], CAP);

        // ---- rank-sort (asc for min list / desc for max list), CAP<=96 ----
        {
            const int sside = (t < CAP) ? 0 : 1;
            const int tl    = (t < CAP) ? t : t - CAP;
            const int n     = sside ? n1 : n0;
            if (t < 2 * CAP && tl < n) {
                float vme = cv[sside][tl];
                int r = 0;
                if (sside == 0) {
                    for (int j = 0; j < n; j++) {
                        float vj = cv[0][j];
                        r += (vj < vme) || (vj == vme && j < tl);
                    }
                } else {
                    for (int j = 0; j < n; j++) {
                        float vj = cv[1][j];
                        r += (vj > vme) || (vj == vme && j < tl);
                    }
                }
                sv[sside][r]  = vme;
                sci[sside][r] = ci[sside][tl];
            }
        }
        __syncthreads();

        // ---- low-rate poll for mask completion (thread 0 only) ----
        if (t == 0) {
            const unsigned target = tgt_s;
            while (*(volatile unsigned*)&g_mask_done < target) __nanosleep(1024);
            __threadfence();                       // acquire maskT stores
        }
        __syncthreads();

        // ---- stage candidate mask rows in sorted order ----
        for (int k = t; k < n0 * 16; k += 256) {
            int c = k >> 4;
            cm[0][c][k & 15] = __ldg(&g_maskT[(size_t)sci[0][c] * 16 + (k & 15)]);
        }
        for (int k = t; k < n1 * 16; k += 256) {
            int c = k >> 4;
            cm[1][c][k & 15] = __ldg(&g_maskT[(size_t)sci[1][c] * 16 + (k & 15)]);
        }
        __syncthreads();

        // ---- resolve: thread t -> outputs 2t (min) and 2t+1 (max).
        // Both share the same mask word index wo; bits bo and bo+1.
        const int wo = (2 * t) >> 5;
        const int bo = (2 * t) & 31;
        const float INF  = __int_as_float(0x7F800000);
        const float NINF = __int_as_float(0xFF800000);
        const bool ovf0 = (n_s[0] > CAP);
        const bool ovf1 = (n_s[1] > CAP);

        float amin = INF;
        if (!ovf0) {
            for (int c = 0; c < n0; c++) {
                if (!((cm[0][c][wo] >> bo) & 1u)) { amin = sv[0][c]; break; }
            }
        }
        float amax = NINF;
        if (!ovf1) {
            for (int c = 0; c < n1; c++) {
                if (!((cm[1][c][wo] >> (bo + 1)) & 1u)) { amax = sv[1][c]; break; }
            }
        }

        if (amin == INF) {   // no unmasked candidate (or overflow): full scan
            const float* xr = x + (size_t)b * IN_F;
            for (int i = 0; i < IN_F; i += 8) {
                #pragma unroll
                for (int u = 0; u < 8; u++) {
                    unsigned wd = __ldg(&g_maskT[(size_t)(i + u) * 16 + wo]);
                    if (!((wd >> bo) & 1u)) amin = fminf(amin, __ldg(&xr[i + u]));
                }
            }
        }
        if (amax == NINF) {
            const float* xr = x + (size_t)b * IN_F;
            for (int i = 0; i < IN_F; i += 8) {
                #pragma unroll
                for (int u = 0; u < 8; u++) {
                    unsigned wd = __ldg(&g_maskT[(size_t)(i + u) * 16 + wo]);
                    if (!((wd >> (bo + 1)) & 1u)) amax = fmaxf(amax, __ldg(&xr[i + u]));
                }
            }
        }

        so_out[2 * t]     = fminf(amin, 2.0f);
        so_out[2 * t + 1] = fmaxf(amax, -1.0f);
        __syncthreads();

        // Coalesced float4 stores (128 threads cover 512 outputs)
        if (t < OUT_F / 4) {
            ((float4*)(out + (size_t)b * OUT_F))[t] = ((const float4*)so_out)[t];
        }
    }
}

extern "C" void kernel_launch(void* const* d_in, const int* in_sizes, int n_in,
                              void* d_out, int out_size) {
    const float* x   = (const float*)d_in[0];  // [256, 1024]
    const float* etc = (const float*)d_in[1];  // [512, 1024, 2]
    const float* un  = (const float*)d_in[2];  // [512, 1024, 2]
    float* out = (float*)d_out;                // [256, 512]

    daa_kernel<<<512, 256>>>(etc, un, x, out);
}